// round 13
// baseline (speedup 1.0000x reference)
#include <cuda_runtime.h>
#include <cuda_bf16.h>
#include <math_constants.h>
#include <cstdint>

#define N_ROWS   16384
#define N_CODES  8192
#define DIM      256

#define TM   128
#define TNI  128
#define ITERS (N_CODES / TNI)   // 64
#define LDAB  272                // 256B int8 row + 16B pad
#define CAP   1024

#define SW_SCALE ((1.0f / 8192.0f) * (1.02f / 127.0f))

#define AS_BYTES (128 * LDAB)    // 34816
#define BS_BYTES (128 * LDAB)
#define OFF_B0   AS_BYTES
#define OFF_B1   (AS_BYTES + BS_BYTES)
#define OFF_RMAX (AS_BYTES + 2 * BS_BYTES)
#define OFF_CNT  (OFF_RMAX + 128 * 4)
#define OFF_MINT (OFF_CNT + 128 * 4)
#define G_SMEM   (OFF_MINT + 128 * 4)

// ---------------------------------------------------------------------------
__device__ float         g_xx[N_ROWS];
__device__ float         g_ax[N_ROWS];
__device__ float         g_sx[N_ROWS];     // per-row x quant scale
__device__ float         g_ww[N_CODES];
__device__ unsigned int  g_cnt[N_ROWS];
__device__ unsigned int  g_cand[(size_t)N_ROWS * CAP];   // code only
__device__ int           g_idx[N_ROWS];
__device__ unsigned int  g_awmax;          // bits of max over codes of sum|w|
__device__ char          g_xq[(size_t)N_ROWS * DIM];
__device__ char          g_wq[(size_t)N_CODES * DIM];

__device__ __forceinline__ void imma16832(int* c, const uint32_t* a,
                                          const uint32_t* b) {
    asm volatile(
        "mma.sync.aligned.m16n8k32.row.col.s32.s8.s8.s32 "
        "{%0,%1,%2,%3}, {%4,%5,%6,%7}, {%8,%9}, {%0,%1,%2,%3};"
        : "+r"(c[0]), "+r"(c[1]), "+r"(c[2]), "+r"(c[3])
        : "r"(a[0]), "r"(a[1]), "r"(a[2]), "r"(a[3]), "r"(b[0]), "r"(b[1]));
}
__device__ __forceinline__ void ldsm4(uint32_t* r, uint32_t addr) {
    asm volatile("ldmatrix.sync.aligned.m8n8.x4.shared.b16 {%0,%1,%2,%3}, [%4];"
                 : "=r"(r[0]), "=r"(r[1]), "=r"(r[2]), "=r"(r[3]) : "r"(addr));
}
__device__ __forceinline__ uint32_t smem_u32(const void* p) {
    uint32_t a;
    asm("{ .reg .u64 t; cvta.to.shared.u64 t, %1; cvt.u32.u64 %0, t; }"
        : "=r"(a) : "l"(p));
    return a;
}
__device__ __forceinline__ void cp16(uint32_t dst, const void* src) {
    asm volatile("cp.async.cg.shared.global [%0], [%1], 16;"
                 :: "r"(dst), "l"(src) : "memory");
}
__device__ __forceinline__ uint32_t pack4(float a, float b, float c, float d,
                                          float inv) {
    int q0 = __float2int_rn(a * inv), q1 = __float2int_rn(b * inv);
    int q2 = __float2int_rn(c * inv), q3 = __float2int_rn(d * inv);
    q0 = max(-127, min(127, q0)); q1 = max(-127, min(127, q1));
    q2 = max(-127, min(127, q2)); q3 = max(-127, min(127, q3));
    return (uint32_t)(q0 & 0xFF) | ((uint32_t)(q1 & 0xFF) << 8)
         | ((uint32_t)(q2 & 0xFF) << 16) | ((uint32_t)(q3 & 0xFF) << 24);
}

// ---------------------------------------------------------------------------
// Kernel P: exact row stats (validated rounding chain) + int8 quantization.
// ---------------------------------------------------------------------------
__global__ void prep_kernel(const float* __restrict__ x,
                            const float* __restrict__ w) {
    int t = blockIdx.x * blockDim.x + threadIdx.x;
    if (t < N_ROWS) {
        const float4* p = (const float4*)(x + (size_t)t * DIM);
        float acc = 0.0f, aacc = 0.0f, amax = 0.0f;
#pragma unroll 8
        for (int j = 0; j < 64; j++) {
            float4 v = p[j];
            acc = __fadd_rn(acc, __fmul_rn(v.x, v.x));
            acc = __fadd_rn(acc, __fmul_rn(v.y, v.y));
            acc = __fadd_rn(acc, __fmul_rn(v.z, v.z));
            acc = __fadd_rn(acc, __fmul_rn(v.w, v.w));
            aacc += fabsf(v.x) + fabsf(v.y) + fabsf(v.z) + fabsf(v.w);
            amax = fmaxf(amax, fmaxf(fmaxf(fabsf(v.x), fabsf(v.y)),
                                     fmaxf(fabsf(v.z), fabsf(v.w))));
        }
        float sx = fmaxf(amax, 1e-20f) / 127.0f;
        float inv = 1.0f / sx;
        g_xx[t] = acc;
        g_ax[t] = aacc;
        g_sx[t] = sx;
        uint4* dst = (uint4*)(g_xq + (size_t)t * DIM);
#pragma unroll 4
        for (int j = 0; j < 16; j++) {
            float4 v0 = p[4 * j], v1 = p[4 * j + 1];
            float4 v2 = p[4 * j + 2], v3 = p[4 * j + 3];
            uint4 o;
            o.x = pack4(v0.x, v0.y, v0.z, v0.w, inv);
            o.y = pack4(v1.x, v1.y, v1.z, v1.w, inv);
            o.z = pack4(v2.x, v2.y, v2.z, v2.w, inv);
            o.w = pack4(v3.x, v3.y, v3.z, v3.w, inv);
            dst[j] = o;
        }
    } else if (t < N_ROWS + N_CODES) {
        int r = t - N_ROWS;
        const float4* p = (const float4*)(w + (size_t)r * DIM);
        float acc = 0.0f, aacc = 0.0f;
        const float inv = 1.0f / SW_SCALE;
        uint4* dst = (uint4*)(g_wq + (size_t)r * DIM);
#pragma unroll 4
        for (int j = 0; j < 16; j++) {
            float4 v0 = p[4 * j], v1 = p[4 * j + 1];
            float4 v2 = p[4 * j + 2], v3 = p[4 * j + 3];
            acc = __fadd_rn(acc, __fmul_rn(v0.x, v0.x));
            acc = __fadd_rn(acc, __fmul_rn(v0.y, v0.y));
            acc = __fadd_rn(acc, __fmul_rn(v0.z, v0.z));
            acc = __fadd_rn(acc, __fmul_rn(v0.w, v0.w));
            acc = __fadd_rn(acc, __fmul_rn(v1.x, v1.x));
            acc = __fadd_rn(acc, __fmul_rn(v1.y, v1.y));
            acc = __fadd_rn(acc, __fmul_rn(v1.z, v1.z));
            acc = __fadd_rn(acc, __fmul_rn(v1.w, v1.w));
            acc = __fadd_rn(acc, __fmul_rn(v2.x, v2.x));
            acc = __fadd_rn(acc, __fmul_rn(v2.y, v2.y));
            acc = __fadd_rn(acc, __fmul_rn(v2.z, v2.z));
            acc = __fadd_rn(acc, __fmul_rn(v2.w, v2.w));
            acc = __fadd_rn(acc, __fmul_rn(v3.x, v3.x));
            acc = __fadd_rn(acc, __fmul_rn(v3.y, v3.y));
            acc = __fadd_rn(acc, __fmul_rn(v3.z, v3.z));
            acc = __fadd_rn(acc, __fmul_rn(v3.w, v3.w));
            aacc += fabsf(v0.x) + fabsf(v0.y) + fabsf(v0.z) + fabsf(v0.w)
                  + fabsf(v1.x) + fabsf(v1.y) + fabsf(v1.z) + fabsf(v1.w)
                  + fabsf(v2.x) + fabsf(v2.y) + fabsf(v2.z) + fabsf(v2.w)
                  + fabsf(v3.x) + fabsf(v3.y) + fabsf(v3.z) + fabsf(v3.w);
            uint4 o;
            o.x = pack4(v0.x, v0.y, v0.z, v0.w, inv);
            o.y = pack4(v1.x, v1.y, v1.z, v1.w, inv);
            o.z = pack4(v2.x, v2.y, v2.z, v2.w, inv);
            o.w = pack4(v3.x, v3.y, v3.z, v3.w, inv);
            dst[j] = o;
        }
        g_ww[r] = acc;
        atomicMax(&g_awmax, __float_as_uint(aacc));  // aacc >= 0
    }
}

// ---------------------------------------------------------------------------
// Kernel G: persistent-A int8 IMMA GEMM (R10 skeleton). grid=128, 512 threads.
// Per-iter: CTA-wide running max of acc (int) in smem; push codes within
// m_int of it. Exact int32 accumulation.
// ---------------------------------------------------------------------------
__global__ void __launch_bounds__(512)
vq_gemm_kernel() {
    extern __shared__ char sm[];
    char* As = sm;
    int*          rmaxs = (int*)(sm + OFF_RMAX);
    unsigned int* cnts  = (unsigned int*)(sm + OFF_CNT);
    int*          mints = (int*)(sm + OFF_MINT);

    const int tid  = threadIdx.x;
    const int wid  = tid >> 5;
    const int lane = tid & 31;
    const int wm   = wid & 1;      // 0..1 -> 64 rows
    const int wn   = wid >> 1;     // 0..7 -> 16 cols
    const int g    = lane >> 2;
    const int tg   = lane & 3;
    const int rowBase = blockIdx.x * TM;

    const uint32_t sm_u  = smem_u32(sm);
    const uint32_t As_u  = sm_u;
    const uint32_t Bu[2] = {sm_u + OFF_B0, sm_u + OFF_B1};

    // prologue: prefetch B tile 0 (128 codes x 256B = 2048 chunks / 512 = 4)
#pragma unroll
    for (int i = 0; i < 4; i++) {
        int c = tid + i * 512;
        int r = c >> 4;
        int k16 = c & 15;
        cp16(Bu[0] + r * LDAB + k16 * 16, g_wq + (size_t)r * DIM + k16 * 16);
    }
    asm volatile("cp.async.commit_group;" ::: "memory");

    // stage A (once)
#pragma unroll
    for (int i = 0; i < 4; i++) {
        int c = tid + i * 512;
        int r = c >> 4;
        int k16 = c & 15;
        uint4 v = *(const uint4*)(g_xq + (size_t)(rowBase + r) * DIM + k16 * 16);
        *(uint4*)(As + r * LDAB + k16 * 16) = v;
    }
    if (tid < 128) {
        rmaxs[tid] = INT_MIN;
        cnts[tid]  = 0u;
        int row = rowBase + tid;
        float sx = g_sx[row];
        float awmax = __uint_as_float(g_awmax);
        // m_s = 2*Deltas + wwmax/2 + tie span + safety (s-domain)
        float m_s = sx * awmax + SW_SCALE * g_ax[row] + 128.0f * sx * SW_SCALE
                  + 2e-6f + g_xx[row] * 1e-6f + 2e-4f;
        mints[tid] = (int)(m_s / (sx * SW_SCALE)) + 1;
    }
    asm volatile("cp.async.wait_group 0;" ::: "memory");
    __syncthreads();

    const int lrow  = (lane & 7) + ((lane >> 3) & 1) * 8;
    const int lkoff = ((lane >> 4) & 1) * 16;

#pragma unroll 1
    for (int it = 0; it < ITERS; it++) {
        // prefetch next B tile
        if (it + 1 < ITERS) {
            const int nb = (it + 1) * TNI;
#pragma unroll
            for (int i = 0; i < 4; i++) {
                int c = tid + i * 512;
                int r = c >> 4;
                int k16 = c & 15;
                cp16(Bu[(it + 1) & 1] + r * LDAB + k16 * 16,
                     g_wq + (size_t)(nb + r) * DIM + k16 * 16);
            }
        }
        asm volatile("cp.async.commit_group;" ::: "memory");

        int acc[4][2][4];
#pragma unroll
        for (int mi = 0; mi < 4; mi++)
#pragma unroll
            for (int ni = 0; ni < 2; ni++)
#pragma unroll
                for (int e = 0; e < 4; e++) acc[mi][ni][e] = 0;

        const uint32_t Bcur = Bu[it & 1];
#pragma unroll
        for (int ks = 0; ks < 8; ks++) {
            uint32_t a[4][4];
#pragma unroll
            for (int mi = 0; mi < 4; mi++)
                ldsm4(a[mi], As_u + (wm * 64 + mi * 16 + lrow) * LDAB
                             + ks * 32 + lkoff);
            uint32_t r[4];
            ldsm4(r, Bcur + (wn * 16 + lrow) * LDAB + ks * 32 + lkoff);
            uint32_t b[2][2];
            b[0][0] = r[0]; b[0][1] = r[2];
            b[1][0] = r[1]; b[1][1] = r[3];
#pragma unroll
            for (int mi = 0; mi < 4; mi++)
#pragma unroll
                for (int ni = 0; ni < 2; ni++)
                    imma16832(acc[mi][ni], a[mi], b[ni]);
        }

        // per-row warp max -> CTA running max (tight threshold)
#pragma unroll
        for (int mi = 0; mi < 4; mi++) {
            int mlo = max(max(acc[mi][0][0], acc[mi][0][1]),
                          max(acc[mi][1][0], acc[mi][1][1]));
            int mhi = max(max(acc[mi][0][2], acc[mi][0][3]),
                          max(acc[mi][1][2], acc[mi][1][3]));
            mlo = max(mlo, __shfl_xor_sync(0xFFFFFFFF, mlo, 1));
            mlo = max(mlo, __shfl_xor_sync(0xFFFFFFFF, mlo, 2));
            mhi = max(mhi, __shfl_xor_sync(0xFFFFFFFF, mhi, 1));
            mhi = max(mhi, __shfl_xor_sync(0xFFFFFFFF, mhi, 2));
            if (tg == 0) {
                atomicMax(&rmaxs[wm * 64 + mi * 16 + g], mlo);
                atomicMax(&rmaxs[wm * 64 + mi * 16 + g + 8], mhi);
            }
        }
        asm volatile("cp.async.wait_group 0;" ::: "memory");
        __syncthreads();

        // push candidates within m_int of CTA running max
        const int c0 = it * TNI + wn * 16 + tg * 2;
#pragma unroll
        for (int mi = 0; mi < 4; mi++) {
#pragma unroll
            for (int h = 0; h < 2; h++) {
                int rl = wm * 64 + mi * 16 + g + h * 8;
                int t = rmaxs[rl] - mints[rl];
                int v0 = acc[mi][0][h * 2 + 0];
                int v1 = acc[mi][0][h * 2 + 1];
                int v2 = acc[mi][1][h * 2 + 0];
                int v3 = acc[mi][1][h * 2 + 1];
                if (v0 >= t || v1 >= t || v2 >= t || v3 >= t) {
                    size_t base = (size_t)(rowBase + rl) * CAP;
                    if (v0 >= t) {
                        unsigned int s_ = atomicAdd(&cnts[rl], 1u);
                        if (s_ < CAP) g_cand[base + s_] = (unsigned int)(c0);
                    }
                    if (v1 >= t) {
                        unsigned int s_ = atomicAdd(&cnts[rl], 1u);
                        if (s_ < CAP) g_cand[base + s_] = (unsigned int)(c0 + 1);
                    }
                    if (v2 >= t) {
                        unsigned int s_ = atomicAdd(&cnts[rl], 1u);
                        if (s_ < CAP) g_cand[base + s_] = (unsigned int)(c0 + 8);
                    }
                    if (v3 >= t) {
                        unsigned int s_ = atomicAdd(&cnts[rl], 1u);
                        if (s_ < CAP) g_cand[base + s_] = (unsigned int)(c0 + 9);
                    }
                }
            }
        }
        __syncthreads();
    }

    if (tid < 128) g_cnt[rowBase + tid] = cnts[tid];
}

// ---------------------------------------------------------------------------
// Kernel F: rescore all pushed candidates exactly (fp32 chain, first-index
// ties). One warp per row; overflow -> exact full scan.
// ---------------------------------------------------------------------------
__global__ void __launch_bounds__(256)
select_kernel(const float* __restrict__ x, const float* __restrict__ w) {
    const int row  = blockIdx.x * 8 + (threadIdx.x >> 5);
    const int lane = threadIdx.x & 31;

    const float xx = g_xx[row];
    const unsigned int cnt = g_cnt[row];
    const float* xr = x + (size_t)row * DIM;

    float bv = CUDART_INF_F;
    int   bi = 0x7fffffff;

    if (cnt <= CAP) {
        const unsigned int* cl = g_cand + (size_t)row * CAP;
        for (unsigned int s = lane; s < cnt; s += 32) {
            int code = (int)cl[s];
            const float* wr = w + (size_t)code * DIM;
            float sdot = 0.0f;
#pragma unroll 8
            for (int k = 0; k < DIM; k++)
                sdot = __fmaf_rn(xr[k], wr[k], sdot);
            float tq = __fadd_rn(xx, g_ww[code]);
            float dq = __fadd_rn(tq, __fmul_rn(-2.0f, sdot));
            if (dq < bv || (dq == bv && code < bi)) { bv = dq; bi = code; }
        }
    } else {
        for (int code = lane; code < N_CODES; code += 32) {
            const float* wr = w + (size_t)code * DIM;
            float sdot = 0.0f;
#pragma unroll 8
            for (int k = 0; k < DIM; k++)
                sdot = __fmaf_rn(xr[k], wr[k], sdot);
            float tq = __fadd_rn(xx, g_ww[code]);
            float dq = __fadd_rn(tq, __fmul_rn(-2.0f, sdot));
            if (dq < bv || (dq == bv && code < bi)) { bv = dq; bi = code; }
        }
    }
#pragma unroll
    for (int off = 16; off > 0; off >>= 1) {
        float ov = __shfl_xor_sync(0xFFFFFFFF, bv, off);
        int   oi = __shfl_xor_sync(0xFFFFFFFF, bi, off);
        if (ov < bv || (ov == bv && oi < bi)) { bv = ov; bi = oi; }
    }
    if (lane == 0) g_idx[row] = bi;
}

// ---------------------------------------------------------------------------
__global__ void gather_kernel(const float* __restrict__ w, float* __restrict__ out,
                              int out_size) {
    int i = blockIdx.x * blockDim.x + threadIdx.x;
    if (i < N_ROWS * (DIM / 4)) {
        int row = i >> 6;
        int c = i & 63;
        int k = g_idx[row];
        float4 v = ((const float4*)(w + (size_t)k * DIM))[c];
        ((float4*)out)[i] = v;
    }
    if (i < N_ROWS && out_size >= N_ROWS * DIM + N_ROWS) {
        out[N_ROWS * DIM + i] = (float)g_idx[i];
    }
}

// ---------------------------------------------------------------------------
extern "C" void kernel_launch(void* const* d_in, const int* in_sizes, int n_in,
                              void* d_out, int out_size) {
    const float* x = (const float*)d_in[0];
    const float* w = (const float*)d_in[1];
    float* out = (float*)d_out;

    static bool attr_set = false;
    if (!attr_set) {
        cudaFuncSetAttribute(vq_gemm_kernel,
                             cudaFuncAttributeMaxDynamicSharedMemorySize, G_SMEM);
        attr_set = true;
    }

    {
        int total = N_ROWS + N_CODES;
        prep_kernel<<<(total + 255) / 256, 256>>>(x, w);
    }
    {
        vq_gemm_kernel<<<N_ROWS / TM, 512, G_SMEM>>>();   // 128 CTAs
    }
    {
        select_kernel<<<N_ROWS / 8, 256>>>(x, w);
    }
    {
        int total4 = N_ROWS * (DIM / 4);
        gather_kernel<<<(total4 + 255) / 256, 256>>>(w, out, out_size);
    }
}

// round 14
// speedup vs baseline: 1.9611x; 1.9611x over previous
#include <cuda_runtime.h>
#include <cuda_bf16.h>
#include <math_constants.h>
#include <cstdint>

#define N_ROWS   16384
#define N_CODES  8192
#define DIM      256

#define TM   128
#define TNI  128
#define ITERS (N_CODES / TNI)   // 64
#define LDAB  528
#define CAP   1024

#define AS_BYTES (128 * LDAB)
#define BS_BYTES (128 * LDAB)
#define OFF_B0   AS_BYTES
#define OFF_B1   (AS_BYTES + BS_BYTES)
#define OFF_RMAX (AS_BYTES + 2 * BS_BYTES)
#define OFF_CNT  (OFF_RMAX + 128 * 4)
#define OFF_MARG (OFF_CNT + 128 * 4)
#define G_SMEM   (OFF_MARG + 128 * 4)

// ---------------------------------------------------------------------------
__device__ float         g_xx[N_ROWS];
__device__ float         g_ax[N_ROWS];
__device__ float         g_ww[N_CODES];
__device__ unsigned int  g_cnt[N_ROWS];
__device__ unsigned int  g_cand[(size_t)N_ROWS * CAP];   // code only
__device__ int           g_idx[N_ROWS];
__device__ unsigned int  g_wmax;
__device__ __nv_bfloat16 g_xbf[N_ROWS * DIM];
__device__ __nv_bfloat16 g_wbf[N_CODES * DIM];

__device__ __forceinline__ unsigned int enc_f(float f) {
    unsigned int u = __float_as_uint(f);
    return (u & 0x80000000u) ? ~u : (u | 0x80000000u);
}
__device__ __forceinline__ float dec_f(unsigned int u) {
    return (u & 0x80000000u) ? __uint_as_float(u ^ 0x80000000u)
                             : __uint_as_float(~u);
}
// margin on the s = x.w scale (d-margin / 2); ww<=4e-6 folded into safety
__device__ __forceinline__ float row_margin_s(float ax, float xx, float wmaxv) {
    return 0.5f * (0.033f * ax * wmaxv + xx * 1.9073486e-6f + 3.1e-4f);
}
__device__ __forceinline__ void mma16816(float* c, const uint32_t* a,
                                         const uint32_t* b) {
    asm volatile(
        "mma.sync.aligned.m16n8k16.row.col.f32.bf16.bf16.f32 "
        "{%0,%1,%2,%3}, {%4,%5,%6,%7}, {%8,%9}, {%0,%1,%2,%3};"
        : "+f"(c[0]), "+f"(c[1]), "+f"(c[2]), "+f"(c[3])
        : "r"(a[0]), "r"(a[1]), "r"(a[2]), "r"(a[3]), "r"(b[0]), "r"(b[1]));
}
__device__ __forceinline__ void ldsm4(uint32_t* r, uint32_t addr) {
    asm volatile("ldmatrix.sync.aligned.m8n8.x4.shared.b16 {%0,%1,%2,%3}, [%4];"
                 : "=r"(r[0]), "=r"(r[1]), "=r"(r[2]), "=r"(r[3]) : "r"(addr));
}
__device__ __forceinline__ uint32_t smem_u32(const void* p) {
    uint32_t a;
    asm("{ .reg .u64 t; cvta.to.shared.u64 t, %1; cvt.u32.u64 %0, t; }"
        : "=r"(a) : "l"(p));
    return a;
}
__device__ __forceinline__ void cp16(uint32_t dst, const void* src) {
    asm volatile("cp.async.cg.shared.global [%0], [%1], 16;"
                 :: "r"(dst), "l"(src) : "memory");
}

// ---------------------------------------------------------------------------
// Kernel P: exact row stats (validated rounding chain) + bf16 casts + wmax.
// ---------------------------------------------------------------------------
__global__ void prep_kernel(const float* __restrict__ x,
                            const float* __restrict__ w) {
    int t = blockIdx.x * blockDim.x + threadIdx.x;
    if (t < N_ROWS) {
        const float4* p = (const float4*)(x + (size_t)t * DIM);
        uint4* dst = (uint4*)(g_xbf + (size_t)t * DIM);
        float acc = 0.0f, aacc = 0.0f;
#pragma unroll 4
        for (int j = 0; j < 32; j++) {
            float4 v0 = p[2 * j], v1 = p[2 * j + 1];
            acc = __fadd_rn(acc, __fmul_rn(v0.x, v0.x));
            acc = __fadd_rn(acc, __fmul_rn(v0.y, v0.y));
            acc = __fadd_rn(acc, __fmul_rn(v0.z, v0.z));
            acc = __fadd_rn(acc, __fmul_rn(v0.w, v0.w));
            acc = __fadd_rn(acc, __fmul_rn(v1.x, v1.x));
            acc = __fadd_rn(acc, __fmul_rn(v1.y, v1.y));
            acc = __fadd_rn(acc, __fmul_rn(v1.z, v1.z));
            acc = __fadd_rn(acc, __fmul_rn(v1.w, v1.w));
            aacc += fabsf(v0.x) + fabsf(v0.y) + fabsf(v0.z) + fabsf(v0.w)
                  + fabsf(v1.x) + fabsf(v1.y) + fabsf(v1.z) + fabsf(v1.w);
            __nv_bfloat162 b0, b1, b2, b3;
            b0.x = __float2bfloat16_rn(v0.x); b0.y = __float2bfloat16_rn(v0.y);
            b1.x = __float2bfloat16_rn(v0.z); b1.y = __float2bfloat16_rn(v0.w);
            b2.x = __float2bfloat16_rn(v1.x); b2.y = __float2bfloat16_rn(v1.y);
            b3.x = __float2bfloat16_rn(v1.z); b3.y = __float2bfloat16_rn(v1.w);
            uint4 o;
            o.x = *(unsigned int*)&b0; o.y = *(unsigned int*)&b1;
            o.z = *(unsigned int*)&b2; o.w = *(unsigned int*)&b3;
            dst[j] = o;
        }
        g_xx[t] = acc;
        g_ax[t] = aacc;
    } else if (t < N_ROWS + N_CODES) {
        int r = t - N_ROWS;
        const float4* p = (const float4*)(w + (size_t)r * DIM);
        uint4* dst = (uint4*)(g_wbf + (size_t)r * DIM);
        float acc = 0.0f, amax = 0.0f;
#pragma unroll 4
        for (int j = 0; j < 32; j++) {
            float4 v0 = p[2 * j], v1 = p[2 * j + 1];
            acc = __fadd_rn(acc, __fmul_rn(v0.x, v0.x));
            acc = __fadd_rn(acc, __fmul_rn(v0.y, v0.y));
            acc = __fadd_rn(acc, __fmul_rn(v0.z, v0.z));
            acc = __fadd_rn(acc, __fmul_rn(v0.w, v0.w));
            acc = __fadd_rn(acc, __fmul_rn(v1.x, v1.x));
            acc = __fadd_rn(acc, __fmul_rn(v1.y, v1.y));
            acc = __fadd_rn(acc, __fmul_rn(v1.z, v1.z));
            acc = __fadd_rn(acc, __fmul_rn(v1.w, v1.w));
            amax = fmaxf(amax, fmaxf(fmaxf(fabsf(v0.x), fabsf(v0.y)),
                                     fmaxf(fabsf(v0.z), fabsf(v0.w))));
            amax = fmaxf(amax, fmaxf(fmaxf(fabsf(v1.x), fabsf(v1.y)),
                                     fmaxf(fabsf(v1.z), fabsf(v1.w))));
            __nv_bfloat162 b0, b1, b2, b3;
            b0.x = __float2bfloat16_rn(v0.x); b0.y = __float2bfloat16_rn(v0.y);
            b1.x = __float2bfloat16_rn(v0.z); b1.y = __float2bfloat16_rn(v0.w);
            b2.x = __float2bfloat16_rn(v1.x); b2.y = __float2bfloat16_rn(v1.y);
            b3.x = __float2bfloat16_rn(v1.z); b3.y = __float2bfloat16_rn(v1.w);
            uint4 o;
            o.x = *(unsigned int*)&b0; o.y = *(unsigned int*)&b1;
            o.z = *(unsigned int*)&b2; o.w = *(unsigned int*)&b3;
            dst[j] = o;
        }
        g_ww[r] = acc;
        atomicMax(&g_wmax, __float_as_uint(amax));
    }
}

// ---------------------------------------------------------------------------
// Kernel G: persistent-A bf16 GEMM (R10 schedule). grid=128, 512 threads.
// Per-iter: CTA-wide running max of s in smem (tight); push codes within
// margin_s of it after syncthreads. Candidates: code only.
// ---------------------------------------------------------------------------
__global__ void __launch_bounds__(512)
vq_gemm_kernel() {
    extern __shared__ char sm[];
    char* As = sm;
    unsigned int* rmaxs = (unsigned int*)(sm + OFF_RMAX);
    unsigned int* cnts  = (unsigned int*)(sm + OFF_CNT);
    float*        margs = (float*)(sm + OFF_MARG);

    const int tid  = threadIdx.x;
    const int wid  = tid >> 5;
    const int lane = tid & 31;
    const int wm   = wid & 1;      // 0..1 -> 64 rows
    const int wn   = wid >> 1;     // 0..7 -> 16 cols
    const int g    = lane >> 2;
    const int tg   = lane & 3;
    const int rowBase = blockIdx.x * TM;

    const uint32_t sm_u  = smem_u32(sm);
    const uint32_t As_u  = sm_u;
    const uint32_t Bu[2] = {sm_u + OFF_B0, sm_u + OFF_B1};

    // prologue: prefetch B tile 0
#pragma unroll
    for (int i = 0; i < 8; i++) {
        int c = tid + i * 512;
        int r = c >> 5;
        int k16 = c & 31;
        cp16(Bu[0] + r * LDAB + k16 * 16, g_wbf + (size_t)r * DIM + k16 * 8);
    }
    asm volatile("cp.async.commit_group;" ::: "memory");

    // stage A (once)
#pragma unroll
    for (int i = 0; i < 8; i++) {
        int c = tid + i * 512;
        int r = c >> 5;
        int k16 = c & 31;
        uint4 v = *(const uint4*)(g_xbf + (size_t)(rowBase + r) * DIM + k16 * 8);
        *(uint4*)(As + r * LDAB + k16 * 16) = v;
    }
    if (tid < 128) {
        rmaxs[tid] = 0u;             // enc_f(-inf) == 0
        cnts[tid]  = 0u;
        int row = rowBase + tid;
        margs[tid] = row_margin_s(g_ax[row], g_xx[row],
                                  __uint_as_float(g_wmax));
    }
    asm volatile("cp.async.wait_group 0;" ::: "memory");
    __syncthreads();

    const int lrow  = (lane & 7) + ((lane >> 3) & 1) * 8;
    const int lkoff = ((lane >> 4) & 1) * 16;

#pragma unroll 1
    for (int it = 0; it < ITERS; it++) {
        // prefetch next B tile
        if (it + 1 < ITERS) {
            const int nb = (it + 1) * TNI;
#pragma unroll
            for (int i = 0; i < 8; i++) {
                int c = tid + i * 512;
                int r = c >> 5;
                int k16 = c & 31;
                cp16(Bu[(it + 1) & 1] + r * LDAB + k16 * 16,
                     g_wbf + (size_t)(nb + r) * DIM + k16 * 8);
            }
        }
        asm volatile("cp.async.commit_group;" ::: "memory");

        float acc[4][2][4];
#pragma unroll
        for (int mi = 0; mi < 4; mi++)
#pragma unroll
            for (int ni = 0; ni < 2; ni++)
#pragma unroll
                for (int e = 0; e < 4; e++) acc[mi][ni][e] = 0.0f;

        const uint32_t Bcur = Bu[it & 1];
#pragma unroll
        for (int ks = 0; ks < 16; ks++) {
            uint32_t a[4][4];
#pragma unroll
            for (int mi = 0; mi < 4; mi++)
                ldsm4(a[mi], As_u + (wm * 64 + mi * 16 + lrow) * LDAB
                             + ks * 32 + lkoff);
            uint32_t r[4];
            ldsm4(r, Bcur + (wn * 16 + lrow) * LDAB + ks * 32 + lkoff);
            uint32_t b[2][2];
            b[0][0] = r[0]; b[0][1] = r[2];
            b[1][0] = r[1]; b[1][1] = r[3];
#pragma unroll
            for (int mi = 0; mi < 4; mi++)
#pragma unroll
                for (int ni = 0; ni < 2; ni++)
                    mma16816(acc[mi][ni], a[mi], b[ni]);
        }

        // per-row warp max of s -> CTA running max (tight threshold)
#pragma unroll
        for (int mi = 0; mi < 4; mi++) {
            float mlo = fmaxf(fmaxf(acc[mi][0][0], acc[mi][0][1]),
                              fmaxf(acc[mi][1][0], acc[mi][1][1]));
            float mhi = fmaxf(fmaxf(acc[mi][0][2], acc[mi][0][3]),
                              fmaxf(acc[mi][1][2], acc[mi][1][3]));
            mlo = fmaxf(mlo, __shfl_xor_sync(0xFFFFFFFF, mlo, 1));
            mlo = fmaxf(mlo, __shfl_xor_sync(0xFFFFFFFF, mlo, 2));
            mhi = fmaxf(mhi, __shfl_xor_sync(0xFFFFFFFF, mhi, 1));
            mhi = fmaxf(mhi, __shfl_xor_sync(0xFFFFFFFF, mhi, 2));
            if (tg == 0) {
                atomicMax(&rmaxs[wm * 64 + mi * 16 + g], enc_f(mlo));
                atomicMax(&rmaxs[wm * 64 + mi * 16 + g + 8], enc_f(mhi));
            }
        }

        asm volatile("cp.async.wait_group 0;" ::: "memory");
        __syncthreads();

        // push candidates: s >= running_max - margin_s (code only)
        const int c0 = it * TNI + wn * 16 + tg * 2;
#pragma unroll
        for (int mi = 0; mi < 4; mi++) {
#pragma unroll
            for (int h = 0; h < 2; h++) {
                int rl = wm * 64 + mi * 16 + g + h * 8;
                float t = dec_f(rmaxs[rl]) - margs[rl];
                float v0 = acc[mi][0][h * 2 + 0];
                float v1 = acc[mi][0][h * 2 + 1];
                float v2 = acc[mi][1][h * 2 + 0];
                float v3 = acc[mi][1][h * 2 + 1];
                if (v0 >= t || v1 >= t || v2 >= t || v3 >= t) {
                    size_t base = (size_t)(rowBase + rl) * CAP;
                    if (v0 >= t) {
                        unsigned int s_ = atomicAdd(&cnts[rl], 1u);
                        if (s_ < CAP) g_cand[base + s_] = (unsigned int)(c0);
                    }
                    if (v1 >= t) {
                        unsigned int s_ = atomicAdd(&cnts[rl], 1u);
                        if (s_ < CAP) g_cand[base + s_] = (unsigned int)(c0 + 1);
                    }
                    if (v2 >= t) {
                        unsigned int s_ = atomicAdd(&cnts[rl], 1u);
                        if (s_ < CAP) g_cand[base + s_] = (unsigned int)(c0 + 8);
                    }
                    if (v3 >= t) {
                        unsigned int s_ = atomicAdd(&cnts[rl], 1u);
                        if (s_ < CAP) g_cand[base + s_] = (unsigned int)(c0 + 9);
                    }
                }
            }
        }
    }

    __syncthreads();
    if (tid < 128) g_cnt[rowBase + tid] = cnts[tid];
}

// ---------------------------------------------------------------------------
// Kernel F: rescore all pushed candidates exactly (fp32 chain, first-index
// ties). One warp per row; overflow -> exact full scan.
// ---------------------------------------------------------------------------
__global__ void __launch_bounds__(256)
select_kernel(const float* __restrict__ x, const float* __restrict__ w) {
    const int row  = blockIdx.x * 8 + (threadIdx.x >> 5);
    const int lane = threadIdx.x & 31;

    const float xx = g_xx[row];
    const unsigned int cnt = g_cnt[row];
    const float* xr = x + (size_t)row * DIM;

    float bv = CUDART_INF_F;
    int   bi = 0x7fffffff;

    if (cnt <= CAP) {
        const unsigned int* cl = g_cand + (size_t)row * CAP;
        for (unsigned int s = lane; s < cnt; s += 32) {
            int code = (int)cl[s];
            const float* wr = w + (size_t)code * DIM;
            float sdot = 0.0f;
#pragma unroll 8
            for (int k = 0; k < DIM; k++)
                sdot = __fmaf_rn(xr[k], wr[k], sdot);
            float tq = __fadd_rn(xx, g_ww[code]);
            float dq = __fadd_rn(tq, __fmul_rn(-2.0f, sdot));
            if (dq < bv || (dq == bv && code < bi)) { bv = dq; bi = code; }
        }
    } else {
        for (int code = lane; code < N_CODES; code += 32) {
            const float* wr = w + (size_t)code * DIM;
            float sdot = 0.0f;
#pragma unroll 8
            for (int k = 0; k < DIM; k++)
                sdot = __fmaf_rn(xr[k], wr[k], sdot);
            float tq = __fadd_rn(xx, g_ww[code]);
            float dq = __fadd_rn(tq, __fmul_rn(-2.0f, sdot));
            if (dq < bv || (dq == bv && code < bi)) { bv = dq; bi = code; }
        }
    }
#pragma unroll
    for (int off = 16; off > 0; off >>= 1) {
        float ov = __shfl_xor_sync(0xFFFFFFFF, bv, off);
        int   oi = __shfl_xor_sync(0xFFFFFFFF, bi, off);
        if (ov < bv || (ov == bv && oi < bi)) { bv = ov; bi = oi; }
    }
    if (lane == 0) g_idx[row] = bi;
}

// ---------------------------------------------------------------------------
__global__ void gather_kernel(const float* __restrict__ w, float* __restrict__ out,
                              int out_size) {
    int i = blockIdx.x * blockDim.x + threadIdx.x;
    if (i < N_ROWS * (DIM / 4)) {
        int row = i >> 6;
        int c = i & 63;
        int k = g_idx[row];
        float4 v = ((const float4*)(w + (size_t)k * DIM))[c];
        ((float4*)out)[i] = v;
    }
    if (i < N_ROWS && out_size >= N_ROWS * DIM + N_ROWS) {
        out[N_ROWS * DIM + i] = (float)g_idx[i];
    }
}

// ---------------------------------------------------------------------------
extern "C" void kernel_launch(void* const* d_in, const int* in_sizes, int n_in,
                              void* d_out, int out_size) {
    const float* x = (const float*)d_in[0];
    const float* w = (const float*)d_in[1];
    float* out = (float*)d_out;

    static bool attr_set = false;
    if (!attr_set) {
        cudaFuncSetAttribute(vq_gemm_kernel,
                             cudaFuncAttributeMaxDynamicSharedMemorySize, G_SMEM);
        attr_set = true;
    }

    {
        int total = N_ROWS + N_CODES;
        prep_kernel<<<(total + 255) / 256, 256>>>(x, w);
    }
    {
        vq_gemm_kernel<<<N_ROWS / TM, 512, G_SMEM>>>();   // 128 CTAs
    }
    {
        select_kernel<<<N_ROWS / 8, 256>>>(x, w);
    }
    {
        int total4 = N_ROWS * (DIM / 4);
        gather_kernel<<<(total4 + 255) / 256, 256>>>(w, out, out_size);
    }
}

// round 15
// speedup vs baseline: 2.5796x; 1.3154x over previous
#include <cuda_runtime.h>
#include <cuda_bf16.h>
#include <cuda_fp16.h>
#include <math_constants.h>
#include <cstdint>

#define N_ROWS   16384
#define N_CODES  8192
#define DIM      256

#define TM   128
#define TNI  128
#define ITERS (N_CODES / TNI)   // 64
#define LDAB  528
#define CAP   1024

#define AS_BYTES (128 * LDAB)
#define BS_BYTES (128 * LDAB)
#define OFF_B0   AS_BYTES
#define OFF_B1   (AS_BYTES + BS_BYTES)
#define OFF_RMIN (AS_BYTES + 2 * BS_BYTES)
#define OFF_CNT  (OFF_RMIN + 128 * 4)
#define OFF_MARG (OFF_CNT + 128 * 4)
#define G_SMEM   (OFF_MARG + 128 * 4)

// ---------------------------------------------------------------------------
__device__ float         g_xx[N_ROWS];
__device__ float         g_ax[N_ROWS];
__device__ float         g_ww[N_CODES];
__device__ unsigned int  g_rowmin[N_ROWS];
__device__ unsigned int  g_cnt[N_ROWS];
__device__ uint2         g_cand[(size_t)N_ROWS * CAP];
__device__ int           g_idx[N_ROWS];
__device__ unsigned int  g_wmax;
__device__ __nv_bfloat16 g_xbf[N_ROWS * DIM];
__device__ __nv_bfloat16 g_wbf[N_CODES * DIM];

__device__ __forceinline__ unsigned int enc_f(float f) {
    unsigned int u = __float_as_uint(f);
    return (u & 0x80000000u) ? ~u : (u | 0x80000000u);
}
__device__ __forceinline__ float dec_f(unsigned int u) {
    return (u & 0x80000000u) ? __uint_as_float(u ^ 0x80000000u)
                             : __uint_as_float(~u);
}
__device__ __forceinline__ float row_margin(float ax, float xx, float wmaxv) {
    return 0.033f * ax * wmaxv + xx * 1.9073486e-6f + 2e-4f;
}
__device__ __forceinline__ void mma16816(float* c, const uint32_t* a,
                                         const uint32_t* b) {
    asm volatile(
        "mma.sync.aligned.m16n8k16.row.col.f32.bf16.bf16.f32 "
        "{%0,%1,%2,%3}, {%4,%5,%6,%7}, {%8,%9}, {%0,%1,%2,%3};"
        : "+f"(c[0]), "+f"(c[1]), "+f"(c[2]), "+f"(c[3])
        : "r"(a[0]), "r"(a[1]), "r"(a[2]), "r"(a[3]), "r"(b[0]), "r"(b[1]));
}
__device__ __forceinline__ void ldsm4(uint32_t* r, uint32_t addr) {
    asm volatile("ldmatrix.sync.aligned.m8n8.x4.shared.b16 {%0,%1,%2,%3}, [%4];"
                 : "=r"(r[0]), "=r"(r[1]), "=r"(r[2]), "=r"(r[3]) : "r"(addr));
}
__device__ __forceinline__ uint32_t smem_u32(const void* p) {
    uint32_t a;
    asm("{ .reg .u64 t; cvta.to.shared.u64 t, %1; cvt.u32.u64 %0, t; }"
        : "=r"(a) : "l"(p));
    return a;
}
__device__ __forceinline__ void cp16(uint32_t dst, const void* src) {
    asm volatile("cp.async.cg.shared.global [%0], [%1], 16;"
                 :: "r"(dst), "l"(src) : "memory");
}

// ---------------------------------------------------------------------------
// Kernel P: exact row stats + bf16 casts + wmax.
// ---------------------------------------------------------------------------
__global__ void prep_kernel(const float* __restrict__ x,
                            const float* __restrict__ w) {
    int t = blockIdx.x * blockDim.x + threadIdx.x;
    if (t < N_ROWS) {
        const float4* p = (const float4*)(x + (size_t)t * DIM);
        uint4* dst = (uint4*)(g_xbf + (size_t)t * DIM);
        float acc = 0.0f, aacc = 0.0f;
#pragma unroll 4
        for (int j = 0; j < 32; j++) {
            float4 v0 = p[2 * j], v1 = p[2 * j + 1];
            acc = __fadd_rn(acc, __fmul_rn(v0.x, v0.x));
            acc = __fadd_rn(acc, __fmul_rn(v0.y, v0.y));
            acc = __fadd_rn(acc, __fmul_rn(v0.z, v0.z));
            acc = __fadd_rn(acc, __fmul_rn(v0.w, v0.w));
            acc = __fadd_rn(acc, __fmul_rn(v1.x, v1.x));
            acc = __fadd_rn(acc, __fmul_rn(v1.y, v1.y));
            acc = __fadd_rn(acc, __fmul_rn(v1.z, v1.z));
            acc = __fadd_rn(acc, __fmul_rn(v1.w, v1.w));
            aacc += fabsf(v0.x) + fabsf(v0.y) + fabsf(v0.z) + fabsf(v0.w)
                  + fabsf(v1.x) + fabsf(v1.y) + fabsf(v1.z) + fabsf(v1.w);
            __nv_bfloat162 b0, b1, b2, b3;
            b0.x = __float2bfloat16_rn(v0.x); b0.y = __float2bfloat16_rn(v0.y);
            b1.x = __float2bfloat16_rn(v0.z); b1.y = __float2bfloat16_rn(v0.w);
            b2.x = __float2bfloat16_rn(v1.x); b2.y = __float2bfloat16_rn(v1.y);
            b3.x = __float2bfloat16_rn(v1.z); b3.y = __float2bfloat16_rn(v1.w);
            uint4 o;
            o.x = *(unsigned int*)&b0; o.y = *(unsigned int*)&b1;
            o.z = *(unsigned int*)&b2; o.w = *(unsigned int*)&b3;
            dst[j] = o;
        }
        g_xx[t] = acc;
        g_ax[t] = aacc;
    } else if (t < N_ROWS + N_CODES) {
        int r = t - N_ROWS;
        const float4* p = (const float4*)(w + (size_t)r * DIM);
        uint4* dst = (uint4*)(g_wbf + (size_t)r * DIM);
        float acc = 0.0f, amax = 0.0f;
#pragma unroll 4
        for (int j = 0; j < 32; j++) {
            float4 v0 = p[2 * j], v1 = p[2 * j + 1];
            acc = __fadd_rn(acc, __fmul_rn(v0.x, v0.x));
            acc = __fadd_rn(acc, __fmul_rn(v0.y, v0.y));
            acc = __fadd_rn(acc, __fmul_rn(v0.z, v0.z));
            acc = __fadd_rn(acc, __fmul_rn(v0.w, v0.w));
            acc = __fadd_rn(acc, __fmul_rn(v1.x, v1.x));
            acc = __fadd_rn(acc, __fmul_rn(v1.y, v1.y));
            acc = __fadd_rn(acc, __fmul_rn(v1.z, v1.z));
            acc = __fadd_rn(acc, __fmul_rn(v1.w, v1.w));
            amax = fmaxf(amax, fmaxf(fmaxf(fabsf(v0.x), fabsf(v0.y)),
                                     fmaxf(fabsf(v0.z), fabsf(v0.w))));
            amax = fmaxf(amax, fmaxf(fmaxf(fabsf(v1.x), fabsf(v1.y)),
                                     fmaxf(fabsf(v1.z), fabsf(v1.w))));
            __nv_bfloat162 b0, b1, b2, b3;
            b0.x = __float2bfloat16_rn(v0.x); b0.y = __float2bfloat16_rn(v0.y);
            b1.x = __float2bfloat16_rn(v0.z); b1.y = __float2bfloat16_rn(v0.w);
            b2.x = __float2bfloat16_rn(v1.x); b2.y = __float2bfloat16_rn(v1.y);
            b3.x = __float2bfloat16_rn(v1.z); b3.y = __float2bfloat16_rn(v1.w);
            uint4 o;
            o.x = *(unsigned int*)&b0; o.y = *(unsigned int*)&b1;
            o.z = *(unsigned int*)&b2; o.w = *(unsigned int*)&b3;
            dst[j] = o;
        }
        g_ww[r] = acc;
        atomicMax(&g_wmax, __float_as_uint(amax));
    }
}

// ---------------------------------------------------------------------------
// Kernel G: persistent-A GEMM. grid=128, 512 threads (16 warps).
// A (128x256 bf16) resident; B streamed in 128-code tiles, 2-deep cp.async.
// Warp tile 64x16 (wm=wid&1 -> 64 rows, wn=wid>>1 -> 16 cols).
// Rows exclusively owned: rowmin + candidate counters in smem.
// ---------------------------------------------------------------------------
__global__ void __launch_bounds__(512)
vq_gemm_kernel() {
    extern __shared__ char sm[];
    char* As = sm;
    unsigned int* rmins = (unsigned int*)(sm + OFF_RMIN);
    unsigned int* cnts  = (unsigned int*)(sm + OFF_CNT);
    float*        margs = (float*)(sm + OFF_MARG);

    const int tid  = threadIdx.x;
    const int wid  = tid >> 5;
    const int lane = tid & 31;
    const int wm   = wid & 1;      // 0..1 -> 64 rows
    const int wn   = wid >> 1;     // 0..7 -> 16 cols
    const int g    = lane >> 2;
    const int tg   = lane & 3;
    const int rowBase = blockIdx.x * TM;

    const uint32_t sm_u  = smem_u32(sm);
    const uint32_t As_u  = sm_u;
    const uint32_t Bu[2] = {sm_u + OFF_B0, sm_u + OFF_B1};

    // prologue: prefetch B tile 0
#pragma unroll
    for (int i = 0; i < 8; i++) {
        int c = tid + i * 512;
        int r = c >> 5;
        int k16 = c & 31;
        cp16(Bu[0] + r * LDAB + k16 * 16, g_wbf + (size_t)r * DIM + k16 * 8);
    }
    asm volatile("cp.async.commit_group;" ::: "memory");

    // stage A (once)
#pragma unroll
    for (int i = 0; i < 8; i++) {
        int c = tid + i * 512;
        int r = c >> 5;
        int k16 = c & 31;
        uint4 v = *(const uint4*)(g_xbf + (size_t)(rowBase + r) * DIM + k16 * 8);
        *(uint4*)(As + r * LDAB + k16 * 16) = v;
    }
    if (tid < 128) {
        rmins[tid] = 0xFFFFFFFFu;
        cnts[tid]  = 0u;
        int row = rowBase + tid;
        margs[tid] = 0.5f * row_margin(g_ax[row], g_xx[row],
                                       __uint_as_float(g_wmax));
    }
    asm volatile("cp.async.wait_group 0;" ::: "memory");
    __syncthreads();

    // per-thread margin/2 for the 8 rows this thread touches
    float m2[4][2];
#pragma unroll
    for (int mi = 0; mi < 4; mi++)
#pragma unroll
        for (int h = 0; h < 2; h++)
            m2[mi][h] = margs[wm * 64 + mi * 16 + g + h * 8];

    float rmax[4][2];   // thread-local running max of s per owned row
#pragma unroll
    for (int mi = 0; mi < 4; mi++)
#pragma unroll
        for (int h = 0; h < 2; h++) rmax[mi][h] = -CUDART_INF_F;

    const int lrow  = (lane & 7) + ((lane >> 3) & 1) * 8;
    const int lkoff = ((lane >> 4) & 1) * 16;

#pragma unroll 1
    for (int it = 0; it < ITERS; it++) {
        // prefetch next B tile
        if (it + 1 < ITERS) {
            const int nb = (it + 1) * TNI;
#pragma unroll
            for (int i = 0; i < 8; i++) {
                int c = tid + i * 512;
                int r = c >> 5;
                int k16 = c & 31;
                cp16(Bu[(it + 1) & 1] + r * LDAB + k16 * 16,
                     g_wbf + (size_t)(nb + r) * DIM + k16 * 8);
            }
        }
        asm volatile("cp.async.commit_group;" ::: "memory");

        float acc[4][2][4];
#pragma unroll
        for (int mi = 0; mi < 4; mi++)
#pragma unroll
            for (int ni = 0; ni < 2; ni++)
#pragma unroll
                for (int e = 0; e < 4; e++) acc[mi][ni][e] = 0.0f;

        const uint32_t Bcur = Bu[it & 1];
#pragma unroll
        for (int ks = 0; ks < 16; ks++) {
            uint32_t a[4][4];
#pragma unroll
            for (int mi = 0; mi < 4; mi++)
                ldsm4(a[mi], As_u + (wm * 64 + mi * 16 + lrow) * LDAB
                             + ks * 32 + lkoff);
            uint32_t r[4];
            ldsm4(r, Bcur + (wn * 16 + lrow) * LDAB + ks * 32 + lkoff);
            uint32_t b[2][2];
            b[0][0] = r[0]; b[0][1] = r[2];
            b[1][0] = r[1]; b[1][1] = r[3];
#pragma unroll
            for (int mi = 0; mi < 4; mi++)
#pragma unroll
                for (int ni = 0; ni < 2; ni++)
                    mma16816(acc[mi][ni], a[mi], b[ni]);
        }

        // cheap epilogue: thread-local running max + margin/2 filter
        const int c0 = it * TNI + wn * 16 + tg * 2;
#pragma unroll
        for (int mi = 0; mi < 4; mi++) {
#pragma unroll
            for (int h = 0; h < 2; h++) {
                float v0 = acc[mi][0][h * 2 + 0];
                float v1 = acc[mi][0][h * 2 + 1];
                float v2 = acc[mi][1][h * 2 + 0];
                float v3 = acc[mi][1][h * 2 + 1];
                float mx = fmaxf(fmaxf(v0, v1), fmaxf(v2, v3));
                rmax[mi][h] = fmaxf(rmax[mi][h], mx);
                float t = rmax[mi][h] - m2[mi][h];
                if (v0 >= t || v1 >= t || v2 >= t || v3 >= t) {
                    int rl = wm * 64 + mi * 16 + g + h * 8;
                    size_t base = (size_t)(rowBase + rl) * CAP;
                    if (v0 >= t) {
                        unsigned int s_ = atomicAdd(&cnts[rl], 1u);
                        if (s_ < CAP) g_cand[base + s_] =
                            make_uint2(enc_f(-2.0f * v0), (unsigned int)(c0));
                    }
                    if (v1 >= t) {
                        unsigned int s_ = atomicAdd(&cnts[rl], 1u);
                        if (s_ < CAP) g_cand[base + s_] =
                            make_uint2(enc_f(-2.0f * v1), (unsigned int)(c0 + 1));
                    }
                    if (v2 >= t) {
                        unsigned int s_ = atomicAdd(&cnts[rl], 1u);
                        if (s_ < CAP) g_cand[base + s_] =
                            make_uint2(enc_f(-2.0f * v2), (unsigned int)(c0 + 8));
                    }
                    if (v3 >= t) {
                        unsigned int s_ = atomicAdd(&cnts[rl], 1u);
                        if (s_ < CAP) g_cand[base + s_] =
                            make_uint2(enc_f(-2.0f * v3), (unsigned int)(c0 + 9));
                    }
                }
            }
        }

        asm volatile("cp.async.wait_group 0;" ::: "memory");
        __syncthreads();
    }

    // combine per-thread running maxes into exact per-row min of a = -2*s
#pragma unroll
    for (int mi = 0; mi < 4; mi++)
#pragma unroll
        for (int h = 0; h < 2; h++) {
            int rl = wm * 64 + mi * 16 + g + h * 8;
            atomicMin(&rmins[rl], enc_f(-2.0f * rmax[mi][h]));
        }
    __syncthreads();
    if (tid < 128) {
        g_rowmin[rowBase + tid] = rmins[tid];
        g_cnt[rowBase + tid]    = cnts[tid];
    }
}

// ---------------------------------------------------------------------------
// Kernel F: per-row candidate rescore (exact fp32, first-index ties).
// ---------------------------------------------------------------------------
__global__ void __launch_bounds__(256)
select_kernel(const float* __restrict__ x, const float* __restrict__ w) {
    const int row  = blockIdx.x * 8 + (threadIdx.x >> 5);
    const int lane = threadIdx.x & 31;

    const float wmaxv = __uint_as_float(g_wmax);
    const float xx = g_xx[row];
    const float thr = dec_f(g_rowmin[row]) + row_margin(g_ax[row], xx, wmaxv);
    const unsigned int cnt = g_cnt[row];
    const float* xr = x + (size_t)row * DIM;

    float bv = CUDART_INF_F;
    int   bi = 0x7fffffff;

    if (cnt <= CAP) {
        const uint2* cl = g_cand + (size_t)row * CAP;
        for (unsigned int s = lane; s < cnt; s += 32) {
            uint2 c = cl[s];
            if (dec_f(c.x) <= thr) {
                int code = (int)c.y;
                const float* wr = w + (size_t)code * DIM;
                float sdot = 0.0f;
#pragma unroll 8
                for (int k = 0; k < DIM; k++)
                    sdot = __fmaf_rn(xr[k], wr[k], sdot);
                float tq = __fadd_rn(xx, g_ww[code]);
                float dq = __fadd_rn(tq, __fmul_rn(-2.0f, sdot));
                if (dq < bv || (dq == bv && code < bi)) { bv = dq; bi = code; }
            }
        }
    } else {
        for (int code = lane; code < N_CODES; code += 32) {
            const float* wr = w + (size_t)code * DIM;
            float sdot = 0.0f;
#pragma unroll 8
            for (int k = 0; k < DIM; k++)
                sdot = __fmaf_rn(xr[k], wr[k], sdot);
            float tq = __fadd_rn(xx, g_ww[code]);
            float dq = __fadd_rn(tq, __fmul_rn(-2.0f, sdot));
            if (dq < bv || (dq == bv && code < bi)) { bv = dq; bi = code; }
        }
    }
#pragma unroll
    for (int off = 16; off > 0; off >>= 1) {
        float ov = __shfl_xor_sync(0xFFFFFFFF, bv, off);
        int   oi = __shfl_xor_sync(0xFFFFFFFF, bi, off);
        if (ov < bv || (ov == bv && oi < bi)) { bv = ov; bi = oi; }
    }
    if (lane == 0) g_idx[row] = bi;
}

// ---------------------------------------------------------------------------
__global__ void gather_kernel(const float* __restrict__ w, float* __restrict__ out,
                              int out_size) {
    int i = blockIdx.x * blockDim.x + threadIdx.x;
    if (i < N_ROWS * (DIM / 4)) {
        int row = i >> 6;
        int c = i & 63;
        int k = g_idx[row];
        float4 v = ((const float4*)(w + (size_t)k * DIM))[c];
        ((float4*)out)[i] = v;
    }
    if (i < N_ROWS && out_size >= N_ROWS * DIM + N_ROWS) {
        out[N_ROWS * DIM + i] = (float)g_idx[i];
    }
}

// ---------------------------------------------------------------------------
extern "C" void kernel_launch(void* const* d_in, const int* in_sizes, int n_in,
                              void* d_out, int out_size) {
    const float* x = (const float*)d_in[0];
    const float* w = (const float*)d_in[1];
    float* out = (float*)d_out;

    static bool attr_set = false;
    if (!attr_set) {
        cudaFuncSetAttribute(vq_gemm_kernel,
                             cudaFuncAttributeMaxDynamicSharedMemorySize, G_SMEM);
        attr_set = true;
    }

    {
        int total = N_ROWS + N_CODES;
        prep_kernel<<<(total + 255) / 256, 256>>>(x, w);
    }
    {
        vq_gemm_kernel<<<N_ROWS / TM, 512, G_SMEM>>>();   // 128 CTAs
    }
    {
        select_kernel<<<N_ROWS / 8, 256>>>(x, w);
    }
    {
        int total4 = N_ROWS * (DIM / 4);
        gather_kernel<<<(total4 + 255) / 256, 256>>>(w, out, out_size);
    }
}

// round 16
// speedup vs baseline: 4.3054x; 1.6690x over previous
#include <cuda_runtime.h>
#include <cuda_bf16.h>
#include <cuda_fp16.h>
#include <math_constants.h>
#include <cstdint>

#define N_ROWS   16384
#define N_CODES  8192
#define DIM      256

#define TM   128
#define TNI  128
#define ITERS (N_CODES / TNI)   // 64
#define LDAB  528
#define CAP   1024

#define AS_BYTES (128 * LDAB)
#define BS_BYTES (128 * LDAB)
#define OFF_B0   AS_BYTES
#define OFF_B1   (AS_BYTES + BS_BYTES)
#define OFF_RMIN (AS_BYTES + 2 * BS_BYTES)
#define OFF_CNT  (OFF_RMIN + 128 * 4)
#define OFF_MARG (OFF_CNT + 128 * 4)
#define G_SMEM   (OFF_MARG + 128 * 4)

// ---------------------------------------------------------------------------
__device__ float         g_xx[N_ROWS];
__device__ float         g_ax[N_ROWS];
__device__ float         g_ww[N_CODES];
__device__ unsigned int  g_rowmin[N_ROWS];
__device__ unsigned int  g_cnt[N_ROWS];
__device__ uint2         g_cand[(size_t)N_ROWS * CAP];
__device__ int           g_idx[N_ROWS];
__device__ unsigned int  g_wmax;
__device__ __nv_bfloat16 g_xbf[N_ROWS * DIM];
__device__ __nv_bfloat16 g_wbf[N_CODES * DIM];

__device__ __forceinline__ unsigned int enc_f(float f) {
    unsigned int u = __float_as_uint(f);
    return (u & 0x80000000u) ? ~u : (u | 0x80000000u);
}
__device__ __forceinline__ float dec_f(unsigned int u) {
    return (u & 0x80000000u) ? __uint_as_float(u ^ 0x80000000u)
                             : __uint_as_float(~u);
}
__device__ __forceinline__ float row_margin(float ax, float xx, float wmaxv) {
    return 0.033f * ax * wmaxv + xx * 1.9073486e-6f + 2e-4f;
}
__device__ __forceinline__ void mma16816(float* c, const uint32_t* a,
                                         const uint32_t* b) {
    asm volatile(
        "mma.sync.aligned.m16n8k16.row.col.f32.bf16.bf16.f32 "
        "{%0,%1,%2,%3}, {%4,%5,%6,%7}, {%8,%9}, {%0,%1,%2,%3};"
        : "+f"(c[0]), "+f"(c[1]), "+f"(c[2]), "+f"(c[3])
        : "r"(a[0]), "r"(a[1]), "r"(a[2]), "r"(a[3]), "r"(b[0]), "r"(b[1]));
}
__device__ __forceinline__ void ldsm4(uint32_t* r, uint32_t addr) {
    asm volatile("ldmatrix.sync.aligned.m8n8.x4.shared.b16 {%0,%1,%2,%3}, [%4];"
                 : "=r"(r[0]), "=r"(r[1]), "=r"(r[2]), "=r"(r[3]) : "r"(addr));
}
__device__ __forceinline__ uint32_t smem_u32(const void* p) {
    uint32_t a;
    asm("{ .reg .u64 t; cvta.to.shared.u64 t, %1; cvt.u32.u64 %0, t; }"
        : "=r"(a) : "l"(p));
    return a;
}
__device__ __forceinline__ void cp16(uint32_t dst, const void* src) {
    asm volatile("cp.async.cg.shared.global [%0], [%1], 16;"
                 :: "r"(dst), "l"(src) : "memory");
}

// ---------------------------------------------------------------------------
// Kernel P: exact row stats + bf16 casts + wmax.
// ---------------------------------------------------------------------------
__global__ void prep_kernel(const float* __restrict__ x,
                            const float* __restrict__ w) {
    int t = blockIdx.x * blockDim.x + threadIdx.x;
    if (t < N_ROWS) {
        const float4* p = (const float4*)(x + (size_t)t * DIM);
        uint4* dst = (uint4*)(g_xbf + (size_t)t * DIM);
        float acc = 0.0f, aacc = 0.0f;
#pragma unroll 4
        for (int j = 0; j < 32; j++) {
            float4 v0 = p[2 * j], v1 = p[2 * j + 1];
            acc = __fadd_rn(acc, __fmul_rn(v0.x, v0.x));
            acc = __fadd_rn(acc, __fmul_rn(v0.y, v0.y));
            acc = __fadd_rn(acc, __fmul_rn(v0.z, v0.z));
            acc = __fadd_rn(acc, __fmul_rn(v0.w, v0.w));
            acc = __fadd_rn(acc, __fmul_rn(v1.x, v1.x));
            acc = __fadd_rn(acc, __fmul_rn(v1.y, v1.y));
            acc = __fadd_rn(acc, __fmul_rn(v1.z, v1.z));
            acc = __fadd_rn(acc, __fmul_rn(v1.w, v1.w));
            aacc += fabsf(v0.x) + fabsf(v0.y) + fabsf(v0.z) + fabsf(v0.w)
                  + fabsf(v1.x) + fabsf(v1.y) + fabsf(v1.z) + fabsf(v1.w);
            __nv_bfloat162 b0, b1, b2, b3;
            b0.x = __float2bfloat16_rn(v0.x); b0.y = __float2bfloat16_rn(v0.y);
            b1.x = __float2bfloat16_rn(v0.z); b1.y = __float2bfloat16_rn(v0.w);
            b2.x = __float2bfloat16_rn(v1.x); b2.y = __float2bfloat16_rn(v1.y);
            b3.x = __float2bfloat16_rn(v1.z); b3.y = __float2bfloat16_rn(v1.w);
            uint4 o;
            o.x = *(unsigned int*)&b0; o.y = *(unsigned int*)&b1;
            o.z = *(unsigned int*)&b2; o.w = *(unsigned int*)&b3;
            dst[j] = o;
        }
        g_xx[t] = acc;
        g_ax[t] = aacc;
    } else if (t < N_ROWS + N_CODES) {
        int r = t - N_ROWS;
        const float4* p = (const float4*)(w + (size_t)r * DIM);
        uint4* dst = (uint4*)(g_wbf + (size_t)r * DIM);
        float acc = 0.0f, amax = 0.0f;
#pragma unroll 4
        for (int j = 0; j < 32; j++) {
            float4 v0 = p[2 * j], v1 = p[2 * j + 1];
            acc = __fadd_rn(acc, __fmul_rn(v0.x, v0.x));
            acc = __fadd_rn(acc, __fmul_rn(v0.y, v0.y));
            acc = __fadd_rn(acc, __fmul_rn(v0.z, v0.z));
            acc = __fadd_rn(acc, __fmul_rn(v0.w, v0.w));
            acc = __fadd_rn(acc, __fmul_rn(v1.x, v1.x));
            acc = __fadd_rn(acc, __fmul_rn(v1.y, v1.y));
            acc = __fadd_rn(acc, __fmul_rn(v1.z, v1.z));
            acc = __fadd_rn(acc, __fmul_rn(v1.w, v1.w));
            amax = fmaxf(amax, fmaxf(fmaxf(fabsf(v0.x), fabsf(v0.y)),
                                     fmaxf(fabsf(v0.z), fabsf(v0.w))));
            amax = fmaxf(amax, fmaxf(fmaxf(fabsf(v1.x), fabsf(v1.y)),
                                     fmaxf(fabsf(v1.z), fabsf(v1.w))));
            __nv_bfloat162 b0, b1, b2, b3;
            b0.x = __float2bfloat16_rn(v0.x); b0.y = __float2bfloat16_rn(v0.y);
            b1.x = __float2bfloat16_rn(v0.z); b1.y = __float2bfloat16_rn(v0.w);
            b2.x = __float2bfloat16_rn(v1.x); b2.y = __float2bfloat16_rn(v1.y);
            b3.x = __float2bfloat16_rn(v1.z); b3.y = __float2bfloat16_rn(v1.w);
            uint4 o;
            o.x = *(unsigned int*)&b0; o.y = *(unsigned int*)&b1;
            o.z = *(unsigned int*)&b2; o.w = *(unsigned int*)&b3;
            dst[j] = o;
        }
        g_ww[r] = acc;
        atomicMax(&g_wmax, __float_as_uint(amax));
    }
}

// ---------------------------------------------------------------------------
// Kernel G: persistent-A GEMM. grid=128, 512 threads (16 warps).
// A (128x256 bf16) resident; B streamed in 128-code tiles, 2-deep cp.async.
// Warp tile 64x16 (wm=wid&1 -> 64 rows, wn=wid>>1 -> 16 cols).
// Rows exclusively owned: rowmin + candidate counters in smem.
// ---------------------------------------------------------------------------
__global__ void __launch_bounds__(512)
vq_gemm_kernel() {
    extern __shared__ char sm[];
    char* As = sm;
    unsigned int* rmins = (unsigned int*)(sm + OFF_RMIN);
    unsigned int* cnts  = (unsigned int*)(sm + OFF_CNT);
    float*        margs = (float*)(sm + OFF_MARG);

    const int tid  = threadIdx.x;
    const int wid  = tid >> 5;
    const int lane = tid & 31;
    const int wm   = wid & 1;      // 0..1 -> 64 rows
    const int wn   = wid >> 1;     // 0..7 -> 16 cols
    const int g    = lane >> 2;
    const int tg   = lane & 3;
    const int rowBase = blockIdx.x * TM;

    const uint32_t sm_u  = smem_u32(sm);
    const uint32_t As_u  = sm_u;
    const uint32_t Bu[2] = {sm_u + OFF_B0, sm_u + OFF_B1};

    // prologue: prefetch B tile 0
#pragma unroll
    for (int i = 0; i < 8; i++) {
        int c = tid + i * 512;
        int r = c >> 5;
        int k16 = c & 31;
        cp16(Bu[0] + r * LDAB + k16 * 16, g_wbf + (size_t)r * DIM + k16 * 8);
    }
    asm volatile("cp.async.commit_group;" ::: "memory");

    // stage A (once)
#pragma unroll
    for (int i = 0; i < 8; i++) {
        int c = tid + i * 512;
        int r = c >> 5;
        int k16 = c & 31;
        uint4 v = *(const uint4*)(g_xbf + (size_t)(rowBase + r) * DIM + k16 * 8);
        *(uint4*)(As + r * LDAB + k16 * 16) = v;
    }
    if (tid < 128) {
        rmins[tid] = 0xFFFFFFFFu;
        cnts[tid]  = 0u;
        int row = rowBase + tid;
        margs[tid] = 0.5f * row_margin(g_ax[row], g_xx[row],
                                       __uint_as_float(g_wmax));
    }
    asm volatile("cp.async.wait_group 0;" ::: "memory");
    __syncthreads();

    const int lrow  = (lane & 7) + ((lane >> 3) & 1) * 8;
    const int lkoff = ((lane >> 4) & 1) * 16;

#pragma unroll 1
    for (int it = 0; it < ITERS; it++) {
        // prefetch next B tile
        if (it + 1 < ITERS) {
            const int nb = (it + 1) * TNI;
#pragma unroll
            for (int i = 0; i < 8; i++) {
                int c = tid + i * 512;
                int r = c >> 5;
                int k16 = c & 31;
                cp16(Bu[(it + 1) & 1] + r * LDAB + k16 * 16,
                     g_wbf + (size_t)(nb + r) * DIM + k16 * 8);
            }
        }
        asm volatile("cp.async.commit_group;" ::: "memory");

        float acc[4][2][4];
#pragma unroll
        for (int mi = 0; mi < 4; mi++)
#pragma unroll
            for (int ni = 0; ni < 2; ni++)
#pragma unroll
                for (int e = 0; e < 4; e++) acc[mi][ni][e] = 0.0f;

        const uint32_t Bcur = Bu[it & 1];
#pragma unroll
        for (int ks = 0; ks < 16; ks++) {
            uint32_t a[4][4];
#pragma unroll
            for (int mi = 0; mi < 4; mi++)
                ldsm4(a[mi], As_u + (wm * 64 + mi * 16 + lrow) * LDAB
                             + ks * 32 + lkoff);
            uint32_t r[4];
            ldsm4(r, Bcur + (wn * 16 + lrow) * LDAB + ks * 32 + lkoff);
            uint32_t b[2][2];
            b[0][0] = r[0]; b[0][1] = r[2];
            b[1][0] = r[1]; b[1][1] = r[3];
#pragma unroll
            for (int mi = 0; mi < 4; mi++)
#pragma unroll
                for (int ni = 0; ni < 2; ni++)
                    mma16816(acc[mi][ni], a[mi], b[ni]);
        }

        // distances + running smem rowmin
        const int c0 = it * TNI + wn * 16 + tg * 2;
        float ww0a = __ldg(&g_ww[c0]),      ww1a = __ldg(&g_ww[c0 + 1]);
        float ww0b = __ldg(&g_ww[c0 + 8]),  ww1b = __ldg(&g_ww[c0 + 9]);
#pragma unroll
        for (int mi = 0; mi < 4; mi++) {
            acc[mi][0][0] = __fmaf_rn(-2.0f, acc[mi][0][0], ww0a);
            acc[mi][0][1] = __fmaf_rn(-2.0f, acc[mi][0][1], ww1a);
            acc[mi][0][2] = __fmaf_rn(-2.0f, acc[mi][0][2], ww0a);
            acc[mi][0][3] = __fmaf_rn(-2.0f, acc[mi][0][3], ww1a);
            acc[mi][1][0] = __fmaf_rn(-2.0f, acc[mi][1][0], ww0b);
            acc[mi][1][1] = __fmaf_rn(-2.0f, acc[mi][1][1], ww1b);
            acc[mi][1][2] = __fmaf_rn(-2.0f, acc[mi][1][2], ww0b);
            acc[mi][1][3] = __fmaf_rn(-2.0f, acc[mi][1][3], ww1b);
            float mlo = fminf(fminf(acc[mi][0][0], acc[mi][0][1]),
                              fminf(acc[mi][1][0], acc[mi][1][1]));
            float mhi = fminf(fminf(acc[mi][0][2], acc[mi][0][3]),
                              fminf(acc[mi][1][2], acc[mi][1][3]));
            mlo = fminf(mlo, __shfl_xor_sync(0xFFFFFFFF, mlo, 1));
            mlo = fminf(mlo, __shfl_xor_sync(0xFFFFFFFF, mlo, 2));
            mhi = fminf(mhi, __shfl_xor_sync(0xFFFFFFFF, mhi, 1));
            mhi = fminf(mhi, __shfl_xor_sync(0xFFFFFFFF, mhi, 2));
            if (tg == 0) {
                atomicMin(&rmins[wm * 64 + mi * 16 + g], enc_f(mlo));
                atomicMin(&rmins[wm * 64 + mi * 16 + g + 8], enc_f(mhi));
            }
        }

        asm volatile("cp.async.wait_group 0;" ::: "memory");
        __syncthreads();

        // push candidates within running-min + margin (superset of final set)
#pragma unroll
        for (int mi = 0; mi < 4; mi++) {
#pragma unroll
            for (int h = 0; h < 2; h++) {
                int rl = wm * 64 + mi * 16 + g + h * 8;
                float thr = dec_f(rmins[rl]) + margs[rl];
#pragma unroll
                for (int ni = 0; ni < 2; ni++) {
#pragma unroll
                    for (int q = 0; q < 2; q++) {
                        float d = acc[mi][ni][h * 2 + q];
                        if (d <= thr) {
                            int code = c0 + ni * 8 + q;
                            unsigned int slot = atomicAdd(&cnts[rl], 1u);
                            if (slot < CAP)
                                g_cand[(size_t)(rowBase + rl) * CAP + slot] =
                                    make_uint2(enc_f(d), (unsigned int)code);
                        }
                    }
                }
            }
        }
    }

    __syncthreads();
    if (tid < 128) {
        g_rowmin[rowBase + tid] = rmins[tid];   // exact final approx-min
        g_cnt[rowBase + tid]    = cnts[tid];
    }
}

// ---------------------------------------------------------------------------
// Kernel F: per-row candidate rescore (exact fp32, first-index ties).
// ---------------------------------------------------------------------------
__global__ void __launch_bounds__(256)
select_kernel(const float* __restrict__ x, const float* __restrict__ w) {
    const int row  = blockIdx.x * 8 + (threadIdx.x >> 5);
    const int lane = threadIdx.x & 31;

    const float wmaxv = __uint_as_float(g_wmax);
    const float xx = g_xx[row];
    const float thr = dec_f(g_rowmin[row]) + row_margin(g_ax[row], xx, wmaxv);
    const unsigned int cnt = g_cnt[row];
    const float* xr = x + (size_t)row * DIM;

    float bv = CUDART_INF_F;
    int   bi = 0x7fffffff;

    if (cnt <= CAP) {
        const uint2* cl = g_cand + (size_t)row * CAP;
        for (unsigned int s = lane; s < cnt; s += 32) {
            uint2 c = cl[s];
            if (dec_f(c.x) <= thr) {
                int code = (int)c.y;
                const float* wr = w + (size_t)code * DIM;
                float sdot = 0.0f;
#pragma unroll 8
                for (int k = 0; k < DIM; k++)
                    sdot = __fmaf_rn(xr[k], wr[k], sdot);
                float tq = __fadd_rn(xx, g_ww[code]);
                float dq = __fadd_rn(tq, __fmul_rn(-2.0f, sdot));
                if (dq < bv || (dq == bv && code < bi)) { bv = dq; bi = code; }
            }
        }
    } else {
        for (int code = lane; code < N_CODES; code += 32) {
            const float* wr = w + (size_t)code * DIM;
            float sdot = 0.0f;
#pragma unroll 8
            for (int k = 0; k < DIM; k++)
                sdot = __fmaf_rn(xr[k], wr[k], sdot);
            float tq = __fadd_rn(xx, g_ww[code]);
            float dq = __fadd_rn(tq, __fmul_rn(-2.0f, sdot));
            if (dq < bv || (dq == bv && code < bi)) { bv = dq; bi = code; }
        }
    }
#pragma unroll
    for (int off = 16; off > 0; off >>= 1) {
        float ov = __shfl_xor_sync(0xFFFFFFFF, bv, off);
        int   oi = __shfl_xor_sync(0xFFFFFFFF, bi, off);
        if (ov < bv || (ov == bv && oi < bi)) { bv = ov; bi = oi; }
    }
    if (lane == 0) g_idx[row] = bi;
}

// ---------------------------------------------------------------------------
__global__ void gather_kernel(const float* __restrict__ w, float* __restrict__ out,
                              int out_size) {
    int i = blockIdx.x * blockDim.x + threadIdx.x;
    if (i < N_ROWS * (DIM / 4)) {
        int row = i >> 6;
        int c = i & 63;
        int k = g_idx[row];
        float4 v = ((const float4*)(w + (size_t)k * DIM))[c];
        ((float4*)out)[i] = v;
    }
    if (i < N_ROWS && out_size >= N_ROWS * DIM + N_ROWS) {
        out[N_ROWS * DIM + i] = (float)g_idx[i];
    }
}

// ---------------------------------------------------------------------------
extern "C" void kernel_launch(void* const* d_in, const int* in_sizes, int n_in,
                              void* d_out, int out_size) {
    const float* x = (const float*)d_in[0];
    const float* w = (const float*)d_in[1];
    float* out = (float*)d_out;

    static bool attr_set = false;
    if (!attr_set) {
        cudaFuncSetAttribute(vq_gemm_kernel,
                             cudaFuncAttributeMaxDynamicSharedMemorySize, G_SMEM);
        attr_set = true;
    }

    {
        int total = N_ROWS + N_CODES;
        prep_kernel<<<(total + 255) / 256, 256>>>(x, w);
    }
    {
        vq_gemm_kernel<<<N_ROWS / TM, 512, G_SMEM>>>();   // 128 CTAs
    }
    {
        select_kernel<<<N_ROWS / 8, 256>>>(x, w);
    }
    {
        int total4 = N_ROWS * (DIM / 4);
        gather_kernel<<<(total4 + 255) / 256, 256>>>(w, out, out_size);
    }
}